// round 10
// baseline (speedup 1.0000x reference)
#include <cuda_runtime.h>

// Problem constants (fixed shapes from setup_inputs)
#define HD 256
#define WD 256
#define HS 128
#define WS 128
#define C1CH 512
#define KD 64
#define COUT 256
#define NB 2
#define PSRC (HS*WS)      // 16384
#define PDST (HD*WD)      // 65536

// Scratch (static device globals — no runtime allocation)
__device__ float g_Kbuf[NB*KD*PSRC];      // K = W2@c2+b2, transposed layout [kk][x*128+y]
__device__ float g_M[NB*C1CH*PSRC];       // M = W1^T K,  transposed layout [c][x*128+y]
__device__ float g_T[NB*PSRC];            // T = b1^T K,  transposed layout
__device__ float g_att[NB*PDST*4];        // softmax(energy)*coef per dest pixel
__device__ float g_outT[NB*COUT*PSRC];    // transposed 'out'

// ---------------- f32x2 helpers (packed dual-FP32 FMA) ----------------
__device__ __forceinline__ unsigned long long bcast2(float a) {
    unsigned long long r;
    asm("mov.b64 %0, {%1, %1};" : "=l"(r) : "f"(a));
    return r;
}
__device__ __forceinline__ void ffma2(unsigned long long& d,
                                      unsigned long long a,
                                      unsigned long long b) {
    asm("fma.rn.f32x2 %0, %1, %2, %0;" : "+l"(d) : "l"(a), "l"(b));
}
__device__ __forceinline__ float2 unpack2(unsigned long long v) {
    float2 f;
    asm("mov.b64 {%0, %1}, %2;" : "=f"(f.x), "=f"(f.y) : "l"(v));
    return f;
}

// ---------------- Kernel T: transpose out [h][w] -> out_t [w][h] ----------------
__global__ void transpose_out_kernel(const float* __restrict__ out) {
    __shared__ float tile[32][33];
    int bc = blockIdx.z;                       // b*COUT + c
    const float* src = out + (size_t)bc * PSRC;
    float*       dst = g_outT + (size_t)bc * PSRC;
    int h0 = blockIdx.y * 32, w0 = blockIdx.x * 32;
    int tx = threadIdx.x;
    #pragma unroll
    for (int i = threadIdx.y; i < 32; i += 8)
        tile[i][tx] = src[(size_t)(h0 + i) * WS + w0 + tx];
    __syncthreads();
    #pragma unroll
    for (int i = threadIdx.y; i < 32; i += 8)
        dst[(size_t)(w0 + i) * HS + h0 + tx] = tile[tx][i];
}

// ---------------- Kernel A1: Kbuf_t = W2 @ c2 + b2 (M=64,K=512,N=16384 per batch) ----
__global__ void __launch_bounds__(256) gemmK_kernel(const float* __restrict__ c2,
                                                    const float* __restrict__ W2,
                                                    const float* __restrict__ b2) {
    __shared__ __align__(16) float As[32][68];   // As[k][kk]
    __shared__ __align__(16) float Bs[32][128];  // Bs[k][j]
    int b  = blockIdx.y;
    int jt = blockIdx.x;                         // == src row h
    int tid = threadIdx.x;
    int tx = tid & 31, ty = tid >> 5;
    int kk0 = ty * 8;

    unsigned long long acc[8][2];
    #pragma unroll
    for (int i = 0; i < 8; i++) { acc[i][0] = 0ull; acc[i][1] = 0ull; }

    const float* c2p = c2 + (size_t)b * C1CH * PSRC + (size_t)jt * 128;

    for (int k0 = 0; k0 < C1CH; k0 += 32) {
        for (int idx = tid; idx < 64 * 32; idx += 256) {
            int kk = idx >> 5, k = idx & 31;
            As[k][kk] = W2[kk * C1CH + k0 + k];
        }
        for (int idx = tid; idx < 1024; idx += 256) {
            int r = idx >> 5, c4 = idx & 31;
            *(float4*)&Bs[r][c4 * 4] =
                *(const float4*)&c2p[(size_t)(k0 + r) * PSRC + c4 * 4];
        }
        __syncthreads();
        #pragma unroll
        for (int k = 0; k < 32; k++) {
            float4 a0 = *(const float4*)&As[k][kk0];
            float4 a1 = *(const float4*)&As[k][kk0 + 4];
            unsigned long long bA = *(const unsigned long long*)&Bs[k][2 * tx];
            unsigned long long bB = *(const unsigned long long*)&Bs[k][64 + 2 * tx];
            unsigned long long p;
            p = bcast2(a0.x); ffma2(acc[0][0], p, bA); ffma2(acc[0][1], p, bB);
            p = bcast2(a0.y); ffma2(acc[1][0], p, bA); ffma2(acc[1][1], p, bB);
            p = bcast2(a0.z); ffma2(acc[2][0], p, bA); ffma2(acc[2][1], p, bB);
            p = bcast2(a0.w); ffma2(acc[3][0], p, bA); ffma2(acc[3][1], p, bB);
            p = bcast2(a1.x); ffma2(acc[4][0], p, bA); ffma2(acc[4][1], p, bB);
            p = bcast2(a1.y); ffma2(acc[5][0], p, bA); ffma2(acc[5][1], p, bB);
            p = bcast2(a1.z); ffma2(acc[6][0], p, bA); ffma2(acc[6][1], p, bB);
            p = bcast2(a1.w); ffma2(acc[7][0], p, bA); ffma2(acc[7][1], p, bB);
        }
        __syncthreads();
    }
    float* kb = g_Kbuf + (size_t)b * KD * PSRC;
    #pragma unroll
    for (int i = 0; i < 8; i++) {
        float bias = b2[kk0 + i];
        #pragma unroll
        for (int l = 0; l < 2; l++) {
            float2 v = unpack2(acc[i][l]);
            int w = l * 64 + 2 * tx;
            kb[(size_t)(kk0 + i) * PSRC + (size_t)w * HS + jt]       = v.x + bias;
            kb[(size_t)(kk0 + i) * PSRC + (size_t)(w + 1) * HS + jt] = v.y + bias;
        }
    }
}

// ---------------- Kernel A2: M_t = W1^T @ Kbuf_t + T = b1^T Kbuf_t ----------------
__global__ void __launch_bounds__(256) gemmM_kernel(const float* __restrict__ W1,
                                                    const float* __restrict__ b1) {
    __shared__ __align__(16) float As[32][64];   // As[k][cc]
    __shared__ __align__(16) float Bs[32][128];  // Bs[k][j']
    int b  = blockIdx.z;
    int ct = blockIdx.y;
    int jt = blockIdx.x;
    int c0 = ct * 64;
    int tid = threadIdx.x;
    int tx = tid & 31, ty = tid >> 5;
    int cc0 = ty * 8;

    const float* kb = g_Kbuf + (size_t)b * KD * PSRC + (size_t)jt * 128;

    unsigned long long acc[8][2];
    #pragma unroll
    for (int i = 0; i < 8; i++) { acc[i][0] = 0ull; acc[i][1] = 0ull; }
    float Tacc = 0.f;

    for (int k0 = 0; k0 < KD; k0 += 32) {
        for (int idx = tid; idx < 512; idx += 256) {
            int k = idx >> 4, c4 = idx & 15;
            *(float4*)&As[k][c4 * 4] =
                *(const float4*)&W1[(size_t)(k0 + k) * C1CH + c0 + c4 * 4];
        }
        for (int idx = tid; idx < 1024; idx += 256) {
            int r = idx >> 5, c4 = idx & 31;
            *(float4*)&Bs[r][c4 * 4] =
                *(const float4*)&kb[(size_t)(k0 + r) * PSRC + c4 * 4];
        }
        __syncthreads();

        #pragma unroll
        for (int k = 0; k < 32; k++) {
            float4 a0 = *(const float4*)&As[k][cc0];
            float4 a1 = *(const float4*)&As[k][cc0 + 4];
            unsigned long long bA = *(const unsigned long long*)&Bs[k][2 * tx];
            unsigned long long bB = *(const unsigned long long*)&Bs[k][64 + 2 * tx];
            unsigned long long p;
            p = bcast2(a0.x); ffma2(acc[0][0], p, bA); ffma2(acc[0][1], p, bB);
            p = bcast2(a0.y); ffma2(acc[1][0], p, bA); ffma2(acc[1][1], p, bB);
            p = bcast2(a0.z); ffma2(acc[2][0], p, bA); ffma2(acc[2][1], p, bB);
            p = bcast2(a0.w); ffma2(acc[3][0], p, bA); ffma2(acc[3][1], p, bB);
            p = bcast2(a1.x); ffma2(acc[4][0], p, bA); ffma2(acc[4][1], p, bB);
            p = bcast2(a1.y); ffma2(acc[5][0], p, bA); ffma2(acc[5][1], p, bB);
            p = bcast2(a1.z); ffma2(acc[6][0], p, bA); ffma2(acc[6][1], p, bB);
            p = bcast2(a1.w); ffma2(acc[7][0], p, bA); ffma2(acc[7][1], p, bB);
        }
        if (ct == 0 && tid < 128) {
            #pragma unroll
            for (int k = 0; k < 32; k++)
                Tacc += __ldg(&b1[k0 + k]) * Bs[k][tid];
        }
        __syncthreads();
    }

    #pragma unroll
    for (int i = 0; i < 8; i++) {
        float* Mp = g_M + (size_t)(b * C1CH + c0 + cc0 + i) * PSRC + (size_t)jt * 128;
        *(float2*)&Mp[2 * tx]      = unpack2(acc[i][0]);
        *(float2*)&Mp[64 + 2 * tx] = unpack2(acc[i][1]);
    }
    if (ct == 0 && tid < 128)
        g_T[b * PSRC + jt * 128 + tid] = Tacc;
}

// ---------------- Kernel B: energy (c1 . M) + T, softmax*coef -> att --------------
// Grid (2*HD, NB): block = half a dest row (64 dY-pairs). 256 threads = 4 channel
// groups x 64 pairs; groups 1-3 store partials, group 0 combines + softmax.
__global__ void __launch_bounds__(256) energy_kernel(const float* __restrict__ c1) {
    __shared__ float red[3][8][64];
    int b = blockIdx.y;
    int bx = blockIdx.x;
    int dX = bx >> 1, seg = bx & 1;
    int tid = threadIdx.x;
    int g = tid >> 6, t = tid & 63;
    int tp = seg * 64 + t;                   // pair index in [0,128)

    float sx = (dX + 0.5f) * 0.5f - 0.5f;
    int x0  = (int)floorf(sx);
    int x1  = (x0 + 1 < HS - 1) ? x0 + 1 : HS - 1;
    int x00 = x0 > 0 ? x0 : 0;

    float sya = (2 * tp + 0.5f) * 0.5f - 0.5f;       // = tp - 0.25
    float syb = (2 * tp + 1 + 0.5f) * 0.5f - 0.5f;   // = tp + 0.25
    int y0a = (int)floorf(sya);
    int y1a = (y0a + 1 < WS - 1) ? y0a + 1 : WS - 1;
    int y00a = y0a > 0 ? y0a : 0;
    int y0b = (int)floorf(syb);
    int y1b = (y0b + 1 < WS - 1) ? y0b + 1 : WS - 1;
    int y00b = y0b > 0 ? y0b : 0;
    int yA = y00a, yB = y1a, yC = y1b;

    int cbase = g * (C1CH / 4);
    const float* M0 = g_M + (size_t)(b * C1CH + cbase) * PSRC + (size_t)x00 * HS;
    const float* M1 = g_M + (size_t)(b * C1CH + cbase) * PSRC + (size_t)x1 * HS;
    const float* q  = c1 + (size_t)(b * C1CH + cbase) * PDST + (size_t)dX * WD + 2 * tp;

    float e0 = 0, e1 = 0, e2 = 0, e3 = 0, e4 = 0, e5 = 0, e6 = 0, e7 = 0;
    #pragma unroll 4
    for (int c = 0; c < C1CH / 4; c++) {
        float2 qq = *(const float2*)(q + (size_t)c * PDST);
        const float* m0 = M0 + (size_t)c * PSRC;
        const float* m1 = M1 + (size_t)c * PSRC;
        float ma0 = m0[yA], mb0 = m0[yB], mc0 = m0[yC];
        float ma1 = m1[yA], mb1 = m1[yB], mc1 = m1[yC];
        e0 += qq.x * ma0; e1 += qq.x * mb0; e2 += qq.x * ma1; e3 += qq.x * mb1;
        e4 += qq.y * mb0; e5 += qq.y * mc0; e6 += qq.y * mb1; e7 += qq.y * mc1;
    }
    if (g > 0) {
        float* rg = &red[g - 1][0][t];
        rg[0 * 64] = e0; rg[1 * 64] = e1; rg[2 * 64] = e2; rg[3 * 64] = e3;
        rg[4 * 64] = e4; rg[5 * 64] = e5; rg[6 * 64] = e6; rg[7 * 64] = e7;
    }
    __syncthreads();
    if (g > 0) return;
    e0 += red[0][0][t] + red[1][0][t] + red[2][0][t];
    e1 += red[0][1][t] + red[1][1][t] + red[2][1][t];
    e2 += red[0][2][t] + red[1][2][t] + red[2][2][t];
    e3 += red[0][3][t] + red[1][3][t] + red[2][3][t];
    e4 += red[0][4][t] + red[1][4][t] + red[2][4][t];
    e5 += red[0][5][t] + red[1][5][t] + red[2][5][t];
    e6 += red[0][6][t] + red[1][6][t] + red[2][6][t];
    e7 += red[0][7][t] + red[1][7][t] + red[2][7][t];

    const float* T0 = g_T + b * PSRC + x00 * HS;
    const float* T1 = g_T + b * PSRC + x1 * HS;
    e0 += T0[y00a]; e1 += T0[y1a]; e2 += T1[y00a]; e3 += T1[y1a];
    e4 += T0[y00b]; e5 += T0[y1b]; e6 += T1[y00b]; e7 += T1[y1b];

    float dx0 = sx - (float)x0;
    float dx1 = (float)x1 - sx;
    float* attp = g_att + ((size_t)b * PDST + (size_t)dX * WD + 2 * tp) * 4;

    {   // pixel A (dY = 2tp)
        float dy0 = sya - (float)y0a, dy1 = (float)y1a - sya;
        float nrm = (float)((x1 - x0) * (y1a - y0a));
        if (nrm == 0.f) nrm = 1.f;
        float inv_n = 1.f / nrm;
        float c0 = dx0 * dy0 * inv_n, c1c = dx0 * dy1 * inv_n;
        float c2c = dx1 * dy0 * inv_n, c3 = dx1 * dy1 * inv_n;
        float mx = fmaxf(fmaxf(e0, e1), fmaxf(e2, e3));
        float x0e = __expf(e0 - mx), x1e = __expf(e1 - mx);
        float x2e = __expf(e2 - mx), x3e = __expf(e3 - mx);
        float inv = 1.f / (x0e + x1e + x2e + x3e);
        float4 a = make_float4(x0e * inv * c0, x1e * inv * c1c,
                               x2e * inv * c2c, x3e * inv * c3);
        *(float4*)attp = a;
    }
    {   // pixel B (dY = 2tp+1)
        float dy0 = syb - (float)y0b, dy1 = (float)y1b - syb;
        float nrm = (float)((x1 - x0) * (y1b - y0b));
        if (nrm == 0.f) nrm = 1.f;
        float inv_n = 1.f / nrm;
        float c0 = dx0 * dy0 * inv_n, c1c = dx0 * dy1 * inv_n;
        float c2c = dx1 * dy0 * inv_n, c3 = dx1 * dy1 * inv_n;
        float mx = fmaxf(fmaxf(e4, e5), fmaxf(e6, e7));
        float x0e = __expf(e4 - mx), x1e = __expf(e5 - mx);
        float x2e = __expf(e6 - mx), x3e = __expf(e7 - mx);
        float inv = 1.f / (x0e + x1e + x2e + x3e);
        float4 a = make_float4(x0e * inv * c0, x1e * inv * c1c,
                               x2e * inv * c2c, x3e * inv * c3);
        *(float4*)(attp + 4) = a;
    }
}

// ---------------- Kernel C: res[c][p] = sum_k out_t[c][s'_k] * att[p][k] ----------
// Grid (HD, 2, NB): blockIdx.y = channel group (128 ch). 256 threads = 2 halves
// x 128 pairs; each half handles 64 channels. No reduction.
__global__ void __launch_bounds__(256) apply_kernel(float* __restrict__ res) {
    int b = blockIdx.z, cg = blockIdx.y, dX = blockIdx.x;
    int tid = threadIdx.x;
    int t = tid & 127, half = tid >> 7;

    float sx = (dX + 0.5f) * 0.5f - 0.5f;
    int x0  = (int)floorf(sx);
    int x1  = (x0 + 1 < HS - 1) ? x0 + 1 : HS - 1;
    int x00 = x0 > 0 ? x0 : 0;
    int yA = t - 1 > 0 ? t - 1 : 0;
    int yB = t;
    int yC = t + 1 < WS - 1 ? t + 1 : WS - 1;

    const float* attp = g_att + ((size_t)b * PDST + (size_t)dX * WD + 2 * t) * 4;
    float4 aA = *(const float4*)attp;
    float4 aB = *(const float4*)(attp + 4);

    int cbase = cg * (COUT / 2) + half * (COUT / 4);
    const float* O0 = g_outT + (size_t)(b * COUT + cbase) * PSRC + (size_t)x00 * HS;
    const float* O1 = g_outT + (size_t)(b * COUT + cbase) * PSRC + (size_t)x1 * HS;
    float* r = res + (size_t)(b * COUT + cbase) * PDST + (size_t)dX * WD + 2 * t;

    #pragma unroll 4
    for (int c = 0; c < COUT / 4; c++) {
        const float* o0 = O0 + (size_t)c * PSRC;
        const float* o1 = O1 + (size_t)c * PSRC;
        float ma0 = o0[yA], mb0 = o0[yB], mc0 = o0[yC];
        float ma1 = o1[yA], mb1 = o1[yB], mc1 = o1[yC];
        float rA = aA.x * ma0 + aA.y * mb0 + aA.z * ma1 + aA.w * mb1;
        float rB = aB.x * mb0 + aB.y * mc0 + aB.z * mb1 + aB.w * mc1;
        *(float2*)(r + (size_t)c * PDST) = make_float2(rA, rB);
    }
}

// -------------------------------- launch --------------------------------
extern "C" void kernel_launch(void* const* d_in, const int* in_sizes, int n_in,
                              void* d_out, int out_size) {
    const float* c1 = (const float*)d_in[0];
    const float* c2 = (const float*)d_in[1];
    const float* out = (const float*)d_in[2];
    const float* W1 = (const float*)d_in[3];
    const float* b1 = (const float*)d_in[4];
    const float* W2 = (const float*)d_in[5];
    const float* b2 = (const float*)d_in[6];
    float* res = (float*)d_out;

    transpose_out_kernel<<<dim3(4, 4, NB * COUT), dim3(32, 8)>>>(out);
    gemmK_kernel<<<dim3(PSRC / 128, NB), 256>>>(c2, W2, b2);
    gemmM_kernel<<<dim3(PSRC / 128, C1CH / 64, NB), 256>>>(W1, b1);
    energy_kernel<<<dim3(HD * 2, NB), 256>>>(c1);
    apply_kernel<<<dim3(HD, 2, NB), 256>>>(res);
}

// round 12
// speedup vs baseline: 1.0401x; 1.0401x over previous
#include <cuda_runtime.h>

// Problem constants (fixed shapes from setup_inputs)
#define HD 256
#define WD 256
#define HS 128
#define WS 128
#define C1CH 512
#define KD 64
#define COUT 256
#define NB 2
#define PSRC (HS*WS)      // 16384
#define PDST (HD*WD)      // 65536

// Scratch (static device globals — no runtime allocation)
__device__ float g_Kbuf[NB*KD*PSRC];      // K = W2@c2+b2, transposed layout [kk][x*128+y]
__device__ float g_M[NB*C1CH*PSRC];       // M = W1^T K,  transposed layout [c][x*128+y]
__device__ float g_T[NB*PSRC];            // T = b1^T K,  transposed layout
__device__ float g_att[NB*PDST*4];        // softmax(energy)*coef per dest pixel
__device__ float g_outT[NB*COUT*PSRC];    // transposed 'out'

// ---------------- f32x2 helpers (packed dual-FP32 FMA) ----------------
__device__ __forceinline__ unsigned long long bcast2(float a) {
    unsigned long long r;
    asm("mov.b64 %0, {%1, %1};" : "=l"(r) : "f"(a));
    return r;
}
__device__ __forceinline__ void ffma2(unsigned long long& d,
                                      unsigned long long a,
                                      unsigned long long b) {
    asm("fma.rn.f32x2 %0, %1, %2, %0;" : "+l"(d) : "l"(a), "l"(b));
}
__device__ __forceinline__ float2 unpack2(unsigned long long v) {
    float2 f;
    asm("mov.b64 {%0, %1}, %2;" : "=f"(f.x), "=f"(f.y) : "l"(v));
    return f;
}

// ---------------- Kernel T: transpose out [h][w] -> out_t [w][h] ----------------
__global__ void transpose_out_kernel(const float* __restrict__ out) {
    __shared__ float tile[32][33];
    int bc = blockIdx.z;                       // b*COUT + c
    const float* src = out + (size_t)bc * PSRC;
    float*       dst = g_outT + (size_t)bc * PSRC;
    int h0 = blockIdx.y * 32, w0 = blockIdx.x * 32;
    int tx = threadIdx.x;
    #pragma unroll
    for (int i = threadIdx.y; i < 32; i += 8)
        tile[i][tx] = src[(size_t)(h0 + i) * WS + w0 + tx];
    __syncthreads();
    #pragma unroll
    for (int i = threadIdx.y; i < 32; i += 8)
        dst[(size_t)(w0 + i) * HS + h0 + tx] = tile[tx][i];
}

// ---------------- Kernel A1: Kbuf_t = W2 @ c2 + b2 (M=64,K=512,N=16384 per batch) ----
// 64-pixel tiles -> 512 blocks (was 256): fixes 21% occupancy hole.
__global__ void __launch_bounds__(256) gemmK_kernel(const float* __restrict__ c2,
                                                    const float* __restrict__ W2,
                                                    const float* __restrict__ b2) {
    __shared__ __align__(16) float As[32][68];   // As[k][kk]
    __shared__ __align__(16) float Bs[32][64];   // Bs[k][j]
    int b  = blockIdx.y;
    int jt = blockIdx.x;                         // 64-pixel tile: h = jt>>1, w base = (jt&1)*64
    int tid = threadIdx.x;
    int tx = tid & 31, ty = tid >> 5;
    int kk0 = ty * 8;

    unsigned long long acc[8];
    #pragma unroll
    for (int i = 0; i < 8; i++) acc[i] = 0ull;

    const float* c2p = c2 + (size_t)b * C1CH * PSRC + (size_t)jt * 64;

    for (int k0 = 0; k0 < C1CH; k0 += 32) {
        for (int idx = tid; idx < 64 * 32; idx += 256) {
            int kk = idx >> 5, k = idx & 31;
            As[k][kk] = W2[kk * C1CH + k0 + k];
        }
        for (int idx = tid; idx < 512; idx += 256) {
            int r = idx >> 4, c4 = idx & 15;
            *(float4*)&Bs[r][c4 * 4] =
                *(const float4*)&c2p[(size_t)(k0 + r) * PSRC + c4 * 4];
        }
        __syncthreads();
        #pragma unroll
        for (int k = 0; k < 32; k++) {
            float4 a0 = *(const float4*)&As[k][kk0];
            float4 a1 = *(const float4*)&As[k][kk0 + 4];
            unsigned long long bA = *(const unsigned long long*)&Bs[k][2 * tx];
            unsigned long long p;
            p = bcast2(a0.x); ffma2(acc[0], p, bA);
            p = bcast2(a0.y); ffma2(acc[1], p, bA);
            p = bcast2(a0.z); ffma2(acc[2], p, bA);
            p = bcast2(a0.w); ffma2(acc[3], p, bA);
            p = bcast2(a1.x); ffma2(acc[4], p, bA);
            p = bcast2(a1.y); ffma2(acc[5], p, bA);
            p = bcast2(a1.z); ffma2(acc[6], p, bA);
            p = bcast2(a1.w); ffma2(acc[7], p, bA);
        }
        __syncthreads();
    }
    // epilogue: +bias, store TRANSPOSED: Kbuf_t[kk][w*128 + h]
    float* kb = g_Kbuf + (size_t)b * KD * PSRC;
    int h  = jt >> 1;
    int w0 = (jt & 1) * 64 + 2 * tx;
    #pragma unroll
    for (int i = 0; i < 8; i++) {
        float bias = b2[kk0 + i];
        float2 v = unpack2(acc[i]);
        kb[(size_t)(kk0 + i) * PSRC + (size_t)w0 * HS + h]       = v.x + bias;
        kb[(size_t)(kk0 + i) * PSRC + (size_t)(w0 + 1) * HS + h] = v.y + bias;
    }
}

// ---------------- Kernel A2: M_t = W1^T @ Kbuf_t + T = b1^T Kbuf_t ----------------
__global__ void __launch_bounds__(256) gemmM_kernel(const float* __restrict__ W1,
                                                    const float* __restrict__ b1) {
    __shared__ __align__(16) float As[32][64];   // As[k][cc]
    __shared__ __align__(16) float Bs[32][128];  // Bs[k][j']
    int b  = blockIdx.z;
    int ct = blockIdx.y;
    int jt = blockIdx.x;
    int c0 = ct * 64;
    int tid = threadIdx.x;
    int tx = tid & 31, ty = tid >> 5;
    int cc0 = ty * 8;

    const float* kb = g_Kbuf + (size_t)b * KD * PSRC + (size_t)jt * 128;

    unsigned long long acc[8][2];
    #pragma unroll
    for (int i = 0; i < 8; i++) { acc[i][0] = 0ull; acc[i][1] = 0ull; }
    float Tacc = 0.f;

    for (int k0 = 0; k0 < KD; k0 += 32) {
        for (int idx = tid; idx < 512; idx += 256) {
            int k = idx >> 4, c4 = idx & 15;
            *(float4*)&As[k][c4 * 4] =
                *(const float4*)&W1[(size_t)(k0 + k) * C1CH + c0 + c4 * 4];
        }
        for (int idx = tid; idx < 1024; idx += 256) {
            int r = idx >> 5, c4 = idx & 31;
            *(float4*)&Bs[r][c4 * 4] =
                *(const float4*)&kb[(size_t)(k0 + r) * PSRC + c4 * 4];
        }
        __syncthreads();

        #pragma unroll
        for (int k = 0; k < 32; k++) {
            float4 a0 = *(const float4*)&As[k][cc0];
            float4 a1 = *(const float4*)&As[k][cc0 + 4];
            unsigned long long bA = *(const unsigned long long*)&Bs[k][2 * tx];
            unsigned long long bB = *(const unsigned long long*)&Bs[k][64 + 2 * tx];
            unsigned long long p;
            p = bcast2(a0.x); ffma2(acc[0][0], p, bA); ffma2(acc[0][1], p, bB);
            p = bcast2(a0.y); ffma2(acc[1][0], p, bA); ffma2(acc[1][1], p, bB);
            p = bcast2(a0.z); ffma2(acc[2][0], p, bA); ffma2(acc[2][1], p, bB);
            p = bcast2(a0.w); ffma2(acc[3][0], p, bA); ffma2(acc[3][1], p, bB);
            p = bcast2(a1.x); ffma2(acc[4][0], p, bA); ffma2(acc[4][1], p, bB);
            p = bcast2(a1.y); ffma2(acc[5][0], p, bA); ffma2(acc[5][1], p, bB);
            p = bcast2(a1.z); ffma2(acc[6][0], p, bA); ffma2(acc[6][1], p, bB);
            p = bcast2(a1.w); ffma2(acc[7][0], p, bA); ffma2(acc[7][1], p, bB);
        }
        if (ct == 0 && tid < 128) {
            #pragma unroll
            for (int k = 0; k < 32; k++)
                Tacc += __ldg(&b1[k0 + k]) * Bs[k][tid];
        }
        __syncthreads();
    }

    #pragma unroll
    for (int i = 0; i < 8; i++) {
        float* Mp = g_M + (size_t)(b * C1CH + c0 + cc0 + i) * PSRC + (size_t)jt * 128;
        *(float2*)&Mp[2 * tx]      = unpack2(acc[i][0]);
        *(float2*)&Mp[64 + 2 * tx] = unpack2(acc[i][1]);
    }
    if (ct == 0 && tid < 128)
        g_T[b * PSRC + jt * 128 + tid] = Tacc;
}

// ---------------- Kernel B: energy (c1 . M) + T, softmax*coef -> att --------------
// R8 structure (measured 97us): grid (HD, NB), 256 thr = two 128-thread halves,
// each reduces 256 of 512 channels (long loop, high MLP); unroll raised 4->8.
__global__ void __launch_bounds__(256) energy_kernel(const float* __restrict__ c1) {
    __shared__ float red[8][128];
    int b = blockIdx.y, dX = blockIdx.x;
    int tid = threadIdx.x;
    int t = tid & 127, half = tid >> 7;

    float sx = (dX + 0.5f) * 0.5f - 0.5f;
    int x0  = (int)floorf(sx);
    int x1  = (x0 + 1 < HS - 1) ? x0 + 1 : HS - 1;
    int x00 = x0 > 0 ? x0 : 0;

    float sya = (2 * t + 0.5f) * 0.5f - 0.5f;         // = t - 0.25
    float syb = (2 * t + 1 + 0.5f) * 0.5f - 0.5f;     // = t + 0.25
    int y0a = (int)floorf(sya);
    int y1a = (y0a + 1 < WS - 1) ? y0a + 1 : WS - 1;
    int y00a = y0a > 0 ? y0a : 0;
    int y0b = (int)floorf(syb);
    int y1b = (y0b + 1 < WS - 1) ? y0b + 1 : WS - 1;
    int y00b = y0b > 0 ? y0b : 0;
    int yA = y00a, yB = y1a, yC = y1b;

    int cbase = half * (C1CH / 2);
    const float* M0 = g_M + (size_t)(b * C1CH + cbase) * PSRC + (size_t)x00 * HS;
    const float* M1 = g_M + (size_t)(b * C1CH + cbase) * PSRC + (size_t)x1 * HS;
    const float* q  = c1 + (size_t)(b * C1CH + cbase) * PDST + (size_t)dX * WD + 2 * t;

    float e0 = 0, e1 = 0, e2 = 0, e3 = 0, e4 = 0, e5 = 0, e6 = 0, e7 = 0;
    #pragma unroll 8
    for (int c = 0; c < C1CH / 2; c++) {
        float2 qq = *(const float2*)(q + (size_t)c * PDST);
        const float* m0 = M0 + (size_t)c * PSRC;
        const float* m1 = M1 + (size_t)c * PSRC;
        float ma0 = m0[yA], mb0 = m0[yB], mc0 = m0[yC];
        float ma1 = m1[yA], mb1 = m1[yB], mc1 = m1[yC];
        e0 += qq.x * ma0; e1 += qq.x * mb0; e2 += qq.x * ma1; e3 += qq.x * mb1;
        e4 += qq.y * mb0; e5 += qq.y * mc0; e6 += qq.y * mb1; e7 += qq.y * mc1;
    }
    if (half == 1) {
        red[0][t] = e0; red[1][t] = e1; red[2][t] = e2; red[3][t] = e3;
        red[4][t] = e4; red[5][t] = e5; red[6][t] = e6; red[7][t] = e7;
    }
    __syncthreads();
    if (half == 1) return;
    e0 += red[0][t]; e1 += red[1][t]; e2 += red[2][t]; e3 += red[3][t];
    e4 += red[4][t]; e5 += red[5][t]; e6 += red[6][t]; e7 += red[7][t];

    const float* T0 = g_T + b * PSRC + x00 * HS;
    const float* T1 = g_T + b * PSRC + x1 * HS;
    e0 += T0[y00a]; e1 += T0[y1a]; e2 += T1[y00a]; e3 += T1[y1a];
    e4 += T0[y00b]; e5 += T0[y1b]; e6 += T1[y00b]; e7 += T1[y1b];

    float dx0 = sx - (float)x0;
    float dx1 = (float)x1 - sx;
    float* attp = g_att + ((size_t)b * PDST + (size_t)dX * WD + 2 * t) * 4;

    {   // pixel A (dY = 2t)
        float dy0 = sya - (float)y0a, dy1 = (float)y1a - sya;
        float nrm = (float)((x1 - x0) * (y1a - y0a));
        if (nrm == 0.f) nrm = 1.f;
        float inv_n = 1.f / nrm;
        float c0 = dx0 * dy0 * inv_n, c1c = dx0 * dy1 * inv_n;
        float c2c = dx1 * dy0 * inv_n, c3 = dx1 * dy1 * inv_n;
        float mx = fmaxf(fmaxf(e0, e1), fmaxf(e2, e3));
        float x0e = __expf(e0 - mx), x1e = __expf(e1 - mx);
        float x2e = __expf(e2 - mx), x3e = __expf(e3 - mx);
        float inv = 1.f / (x0e + x1e + x2e + x3e);
        float4 a = make_float4(x0e * inv * c0, x1e * inv * c1c,
                               x2e * inv * c2c, x3e * inv * c3);
        *(float4*)attp = a;
    }
    {   // pixel B (dY = 2t+1)
        float dy0 = syb - (float)y0b, dy1 = (float)y1b - syb;
        float nrm = (float)((x1 - x0) * (y1b - y0b));
        if (nrm == 0.f) nrm = 1.f;
        float inv_n = 1.f / nrm;
        float c0 = dx0 * dy0 * inv_n, c1c = dx0 * dy1 * inv_n;
        float c2c = dx1 * dy0 * inv_n, c3 = dx1 * dy1 * inv_n;
        float mx = fmaxf(fmaxf(e4, e5), fmaxf(e6, e7));
        float x0e = __expf(e4 - mx), x1e = __expf(e5 - mx);
        float x2e = __expf(e6 - mx), x3e = __expf(e7 - mx);
        float inv = 1.f / (x0e + x1e + x2e + x3e);
        float4 a = make_float4(x0e * inv * c0, x1e * inv * c1c,
                               x2e * inv * c2c, x3e * inv * c3);
        *(float4*)(attp + 4) = a;
    }
}

// ---------------- Kernel C: res[c][p] = sum_k out_t[c][s'_k] * att[p][k] ----------
// Grid (HD, 2, NB) — measured neutral vs R8 config; each half handles 64 channels.
__global__ void __launch_bounds__(256) apply_kernel(float* __restrict__ res) {
    int b = blockIdx.z, cg = blockIdx.y, dX = blockIdx.x;
    int tid = threadIdx.x;
    int t = tid & 127, half = tid >> 7;

    float sx = (dX + 0.5f) * 0.5f - 0.5f;
    int x0  = (int)floorf(sx);
    int x1  = (x0 + 1 < HS - 1) ? x0 + 1 : HS - 1;
    int x00 = x0 > 0 ? x0 : 0;
    int yA = t - 1 > 0 ? t - 1 : 0;
    int yB = t;
    int yC = t + 1 < WS - 1 ? t + 1 : WS - 1;

    const float* attp = g_att + ((size_t)b * PDST + (size_t)dX * WD + 2 * t) * 4;
    float4 aA = *(const float4*)attp;
    float4 aB = *(const float4*)(attp + 4);

    int cbase = cg * (COUT / 2) + half * (COUT / 4);
    const float* O0 = g_outT + (size_t)(b * COUT + cbase) * PSRC + (size_t)x00 * HS;
    const float* O1 = g_outT + (size_t)(b * COUT + cbase) * PSRC + (size_t)x1 * HS;
    float* r = res + (size_t)(b * COUT + cbase) * PDST + (size_t)dX * WD + 2 * t;

    #pragma unroll 4
    for (int c = 0; c < COUT / 4; c++) {
        const float* o0 = O0 + (size_t)c * PSRC;
        const float* o1 = O1 + (size_t)c * PSRC;
        float ma0 = o0[yA], mb0 = o0[yB], mc0 = o0[yC];
        float ma1 = o1[yA], mb1 = o1[yB], mc1 = o1[yC];
        float rA = aA.x * ma0 + aA.y * mb0 + aA.z * ma1 + aA.w * mb1;
        float rB = aB.x * mb0 + aB.y * mc0 + aB.z * mb1 + aB.w * mc1;
        *(float2*)(r + (size_t)c * PDST) = make_float2(rA, rB);
    }
}

// -------------------------------- launch --------------------------------
extern "C" void kernel_launch(void* const* d_in, const int* in_sizes, int n_in,
                              void* d_out, int out_size) {
    const float* c1 = (const float*)d_in[0];
    const float* c2 = (const float*)d_in[1];
    const float* out = (const float*)d_in[2];
    const float* W1 = (const float*)d_in[3];
    const float* b1 = (const float*)d_in[4];
    const float* W2 = (const float*)d_in[5];
    const float* b2 = (const float*)d_in[6];
    float* res = (float*)d_out;

    transpose_out_kernel<<<dim3(4, 4, NB * COUT), dim3(32, 8)>>>(out);
    gemmK_kernel<<<dim3(PSRC / 64, NB), 256>>>(c2, W2, b2);
    gemmM_kernel<<<dim3(PSRC / 128, C1CH / 64, NB), 256>>>(W1, b1);
    energy_kernel<<<dim3(HD, NB), 256>>>(c1);
    apply_kernel<<<dim3(HD, 2, NB), 256>>>(res);
}

// round 13
// speedup vs baseline: 1.1706x; 1.1255x over previous
#include <cuda_runtime.h>

// Problem constants (fixed shapes from setup_inputs)
#define HD 256
#define WD 256
#define HS 128
#define WS 128
#define C1CH 512
#define KD 64
#define COUT 256
#define NB 2
#define PSRC (HS*WS)      // 16384
#define PDST (HD*WD)      // 65536
#define ECC 16            // energy: channels per smem chunk

// Scratch (static device globals — no runtime allocation)
__device__ float g_Kbuf[NB*KD*PSRC];      // K = W2@c2+b2, transposed layout [kk][x*128+y]
__device__ float g_M[NB*C1CH*PSRC];       // M = W1^T K,  transposed layout [c][x*128+y]
__device__ float g_T[NB*PSRC];            // T = b1^T K,  transposed layout
__device__ float g_att[NB*PDST*4];        // softmax(energy)*coef per dest pixel
__device__ float g_outT[NB*COUT*PSRC];    // transposed 'out'

// ---------------- f32x2 helpers (packed dual-FP32 FMA) ----------------
__device__ __forceinline__ unsigned long long bcast2(float a) {
    unsigned long long r;
    asm("mov.b64 %0, {%1, %1};" : "=l"(r) : "f"(a));
    return r;
}
__device__ __forceinline__ void ffma2(unsigned long long& d,
                                      unsigned long long a,
                                      unsigned long long b) {
    asm("fma.rn.f32x2 %0, %1, %2, %0;" : "+l"(d) : "l"(a), "l"(b));
}
__device__ __forceinline__ float2 unpack2(unsigned long long v) {
    float2 f;
    asm("mov.b64 {%0, %1}, %2;" : "=f"(f.x), "=f"(f.y) : "l"(v));
    return f;
}

// ---------------- Kernel T: transpose out [h][w] -> out_t [w][h] ----------------
__global__ void transpose_out_kernel(const float* __restrict__ out) {
    __shared__ float tile[32][33];
    int bc = blockIdx.z;                       // b*COUT + c
    const float* src = out + (size_t)bc * PSRC;
    float*       dst = g_outT + (size_t)bc * PSRC;
    int h0 = blockIdx.y * 32, w0 = blockIdx.x * 32;
    int tx = threadIdx.x;
    #pragma unroll
    for (int i = threadIdx.y; i < 32; i += 8)
        tile[i][tx] = src[(size_t)(h0 + i) * WS + w0 + tx];
    __syncthreads();
    #pragma unroll
    for (int i = threadIdx.y; i < 32; i += 8)
        dst[(size_t)(w0 + i) * HS + h0 + tx] = tile[tx][i];
}

// ---------------- Kernel A1: Kbuf_t = W2 @ c2 + b2 — R8 version (measured best) ----
__global__ void __launch_bounds__(256) gemmK_kernel(const float* __restrict__ c2,
                                                    const float* __restrict__ W2,
                                                    const float* __restrict__ b2) {
    __shared__ __align__(16) float As[32][68];   // As[k][kk]
    __shared__ __align__(16) float Bs[32][128];  // Bs[k][j]
    int b  = blockIdx.y;
    int jt = blockIdx.x;                         // == src row h
    int tid = threadIdx.x;
    int tx = tid & 31, ty = tid >> 5;
    int kk0 = ty * 8;

    unsigned long long acc[8][2];
    #pragma unroll
    for (int i = 0; i < 8; i++) { acc[i][0] = 0ull; acc[i][1] = 0ull; }

    const float* c2p = c2 + (size_t)b * C1CH * PSRC + (size_t)jt * 128;

    for (int k0 = 0; k0 < C1CH; k0 += 32) {
        for (int idx = tid; idx < 64 * 32; idx += 256) {
            int kk = idx >> 5, k = idx & 31;
            As[k][kk] = W2[kk * C1CH + k0 + k];
        }
        for (int idx = tid; idx < 1024; idx += 256) {
            int r = idx >> 5, c4 = idx & 31;
            *(float4*)&Bs[r][c4 * 4] =
                *(const float4*)&c2p[(size_t)(k0 + r) * PSRC + c4 * 4];
        }
        __syncthreads();
        #pragma unroll
        for (int k = 0; k < 32; k++) {
            float4 a0 = *(const float4*)&As[k][kk0];
            float4 a1 = *(const float4*)&As[k][kk0 + 4];
            unsigned long long bA = *(const unsigned long long*)&Bs[k][2 * tx];
            unsigned long long bB = *(const unsigned long long*)&Bs[k][64 + 2 * tx];
            unsigned long long p;
            p = bcast2(a0.x); ffma2(acc[0][0], p, bA); ffma2(acc[0][1], p, bB);
            p = bcast2(a0.y); ffma2(acc[1][0], p, bA); ffma2(acc[1][1], p, bB);
            p = bcast2(a0.z); ffma2(acc[2][0], p, bA); ffma2(acc[2][1], p, bB);
            p = bcast2(a0.w); ffma2(acc[3][0], p, bA); ffma2(acc[3][1], p, bB);
            p = bcast2(a1.x); ffma2(acc[4][0], p, bA); ffma2(acc[4][1], p, bB);
            p = bcast2(a1.y); ffma2(acc[5][0], p, bA); ffma2(acc[5][1], p, bB);
            p = bcast2(a1.z); ffma2(acc[6][0], p, bA); ffma2(acc[6][1], p, bB);
            p = bcast2(a1.w); ffma2(acc[7][0], p, bA); ffma2(acc[7][1], p, bB);
        }
        __syncthreads();
    }
    float* kb = g_Kbuf + (size_t)b * KD * PSRC;
    #pragma unroll
    for (int i = 0; i < 8; i++) {
        float bias = b2[kk0 + i];
        #pragma unroll
        for (int l = 0; l < 2; l++) {
            float2 v = unpack2(acc[i][l]);
            int w = l * 64 + 2 * tx;
            kb[(size_t)(kk0 + i) * PSRC + (size_t)w * HS + jt]       = v.x + bias;
            kb[(size_t)(kk0 + i) * PSRC + (size_t)(w + 1) * HS + jt] = v.y + bias;
        }
    }
}

// ---------------- Kernel A2: M_t = W1^T @ Kbuf_t + T = b1^T Kbuf_t ----------------
__global__ void __launch_bounds__(256) gemmM_kernel(const float* __restrict__ W1,
                                                    const float* __restrict__ b1) {
    __shared__ __align__(16) float As[32][64];   // As[k][cc]
    __shared__ __align__(16) float Bs[32][128];  // Bs[k][j']
    int b  = blockIdx.z;
    int ct = blockIdx.y;
    int jt = blockIdx.x;
    int c0 = ct * 64;
    int tid = threadIdx.x;
    int tx = tid & 31, ty = tid >> 5;
    int cc0 = ty * 8;

    const float* kb = g_Kbuf + (size_t)b * KD * PSRC + (size_t)jt * 128;

    unsigned long long acc[8][2];
    #pragma unroll
    for (int i = 0; i < 8; i++) { acc[i][0] = 0ull; acc[i][1] = 0ull; }
    float Tacc = 0.f;

    for (int k0 = 0; k0 < KD; k0 += 32) {
        for (int idx = tid; idx < 512; idx += 256) {
            int k = idx >> 4, c4 = idx & 15;
            *(float4*)&As[k][c4 * 4] =
                *(const float4*)&W1[(size_t)(k0 + k) * C1CH + c0 + c4 * 4];
        }
        for (int idx = tid; idx < 1024; idx += 256) {
            int r = idx >> 5, c4 = idx & 31;
            *(float4*)&Bs[r][c4 * 4] =
                *(const float4*)&kb[(size_t)(k0 + r) * PSRC + c4 * 4];
        }
        __syncthreads();

        #pragma unroll
        for (int k = 0; k < 32; k++) {
            float4 a0 = *(const float4*)&As[k][cc0];
            float4 a1 = *(const float4*)&As[k][cc0 + 4];
            unsigned long long bA = *(const unsigned long long*)&Bs[k][2 * tx];
            unsigned long long bB = *(const unsigned long long*)&Bs[k][64 + 2 * tx];
            unsigned long long p;
            p = bcast2(a0.x); ffma2(acc[0][0], p, bA); ffma2(acc[0][1], p, bB);
            p = bcast2(a0.y); ffma2(acc[1][0], p, bA); ffma2(acc[1][1], p, bB);
            p = bcast2(a0.z); ffma2(acc[2][0], p, bA); ffma2(acc[2][1], p, bB);
            p = bcast2(a0.w); ffma2(acc[3][0], p, bA); ffma2(acc[3][1], p, bB);
            p = bcast2(a1.x); ffma2(acc[4][0], p, bA); ffma2(acc[4][1], p, bB);
            p = bcast2(a1.y); ffma2(acc[5][0], p, bA); ffma2(acc[5][1], p, bB);
            p = bcast2(a1.z); ffma2(acc[6][0], p, bA); ffma2(acc[6][1], p, bB);
            p = bcast2(a1.w); ffma2(acc[7][0], p, bA); ffma2(acc[7][1], p, bB);
        }
        if (ct == 0 && tid < 128) {
            #pragma unroll
            for (int k = 0; k < 32; k++)
                Tacc += __ldg(&b1[k0 + k]) * Bs[k][tid];
        }
        __syncthreads();
    }

    #pragma unroll
    for (int i = 0; i < 8; i++) {
        float* Mp = g_M + (size_t)(b * C1CH + c0 + cc0 + i) * PSRC + (size_t)jt * 128;
        *(float2*)&Mp[2 * tx]      = unpack2(acc[i][0]);
        *(float2*)&Mp[64 + 2 * tx] = unpack2(acc[i][1]);
    }
    if (ct == 0 && tid < 128)
        g_T[b * PSRC + jt * 128 + tid] = Tacc;
}

// ---------------- Kernel B: energy — smem-tiled M (NEW) ---------------------------
// One block per (dX, b), 256 threads = one pixel each (dY = tid).
// M rows x00/x1 staged per 16-channel chunk via coalesced float4; gathers -> LDS.
__global__ void __launch_bounds__(256) energy_kernel(const float* __restrict__ c1) {
    __shared__ __align__(16) float Ms[ECC][2][HS];   // 16 KB
    __shared__ float Ts[2][HS];                      // 1 KB
    int b = blockIdx.y, dX = blockIdx.x;
    int t = threadIdx.x;                             // pixel dY = t

    float sx = (dX + 0.5f) * 0.5f - 0.5f;
    int x0  = (int)floorf(sx);
    int x1  = (x0 + 1 < HS - 1) ? x0 + 1 : HS - 1;
    int x00 = x0 > 0 ? x0 : 0;

    float sy = (t + 0.5f) * 0.5f - 0.5f;
    int y0  = (int)floorf(sy);
    int y1  = (y0 + 1 < WS - 1) ? y0 + 1 : WS - 1;
    int y00 = y0 > 0 ? y0 : 0;

    // stage T rows (consumed after loop; first in-loop barrier orders these writes)
    if (t < 128) Ts[0][t] = g_T[b * PSRC + x00 * HS + t];
    else         Ts[1][t - 128] = g_T[b * PSRC + x1 * HS + (t - 128)];

    const float* qbase = c1 + (size_t)b * C1CH * PDST + (size_t)dX * WD + t;
    const float* Mb0 = g_M + (size_t)b * C1CH * PSRC;

    float e0 = 0, e1 = 0, e2 = 0, e3 = 0;
    for (int c0 = 0; c0 < C1CH; c0 += ECC) {
        __syncthreads();   // previous chunk fully consumed (and Ts writes ordered)
        // stage: 1024 float4 over 256 threads, warp-contiguous in y -> coalesced
        const float* Mb = Mb0 + (size_t)c0 * PSRC;
        #pragma unroll
        for (int i = 0; i < 4; i++) {
            int idx = t + i * 256;          // 0..1023
            int cc  = idx >> 6;             // 0..15
            int r   = (idx >> 5) & 1;
            int y4  = (idx & 31) * 4;
            int xr  = r ? x1 : x00;
            *(float4*)&Ms[cc][r][y4] =
                *(const float4*)&Mb[(size_t)cc * PSRC + (size_t)xr * HS + y4];
        }
        __syncthreads();
        // q prefetch: 16 independent coalesced streams (high MLP)
        float qv[ECC];
        #pragma unroll
        for (int cc = 0; cc < ECC; cc++)
            qv[cc] = qbase[(size_t)(c0 + cc) * PDST];
        #pragma unroll
        for (int cc = 0; cc < ECC; cc++) {
            float q = qv[cc];
            e0 += q * Ms[cc][0][y00];   // up_left
            e1 += q * Ms[cc][0][y1];    // up_right
            e2 += q * Ms[cc][1][y00];   // down_left
            e3 += q * Ms[cc][1][y1];    // down_right
        }
    }
    e0 += Ts[0][y00]; e1 += Ts[0][y1]; e2 += Ts[1][y00]; e3 += Ts[1][y1];

    float dx0 = sx - (float)x0, dx1 = (float)x1 - sx;
    float dy0 = sy - (float)y0, dy1 = (float)y1 - sy;
    float nrm = (float)((x1 - x0) * (y1 - y0));
    if (nrm == 0.f) nrm = 1.f;
    float inv_n = 1.f / nrm;
    float c0f = dx0 * dy0 * inv_n, c1f = dx0 * dy1 * inv_n;
    float c2f = dx1 * dy0 * inv_n, c3f = dx1 * dy1 * inv_n;
    float mx = fmaxf(fmaxf(e0, e1), fmaxf(e2, e3));
    float x0e = __expf(e0 - mx), x1e = __expf(e1 - mx);
    float x2e = __expf(e2 - mx), x3e = __expf(e3 - mx);
    float inv = 1.f / (x0e + x1e + x2e + x3e);
    float4 a = make_float4(x0e * inv * c0f, x1e * inv * c1f,
                           x2e * inv * c2f, x3e * inv * c3f);
    *(float4*)(g_att + ((size_t)b * PDST + (size_t)dX * WD + t) * 4) = a;
}

// ---------------- Kernel C: res[c][p] = sum_k out_t[c][s'_k] * att[p][k] ----------
__global__ void __launch_bounds__(256) apply_kernel(float* __restrict__ res) {
    int b = blockIdx.z, cg = blockIdx.y, dX = blockIdx.x;
    int tid = threadIdx.x;
    int t = tid & 127, half = tid >> 7;

    float sx = (dX + 0.5f) * 0.5f - 0.5f;
    int x0  = (int)floorf(sx);
    int x1  = (x0 + 1 < HS - 1) ? x0 + 1 : HS - 1;
    int x00 = x0 > 0 ? x0 : 0;
    int yA = t - 1 > 0 ? t - 1 : 0;
    int yB = t;
    int yC = t + 1 < WS - 1 ? t + 1 : WS - 1;

    const float* attp = g_att + ((size_t)b * PDST + (size_t)dX * WD + 2 * t) * 4;
    float4 aA = *(const float4*)attp;
    float4 aB = *(const float4*)(attp + 4);

    int cbase = cg * (COUT / 2) + half * (COUT / 4);
    const float* O0 = g_outT + (size_t)(b * COUT + cbase) * PSRC + (size_t)x00 * HS;
    const float* O1 = g_outT + (size_t)(b * COUT + cbase) * PSRC + (size_t)x1 * HS;
    float* r = res + (size_t)(b * COUT + cbase) * PDST + (size_t)dX * WD + 2 * t;

    #pragma unroll 4
    for (int c = 0; c < COUT / 4; c++) {
        const float* o0 = O0 + (size_t)c * PSRC;
        const float* o1 = O1 + (size_t)c * PSRC;
        float ma0 = o0[yA], mb0 = o0[yB], mc0 = o0[yC];
        float ma1 = o1[yA], mb1 = o1[yB], mc1 = o1[yC];
        float rA = aA.x * ma0 + aA.y * mb0 + aA.z * ma1 + aA.w * mb1;
        float rB = aB.x * mb0 + aB.y * mc0 + aB.z * mb1 + aB.w * mc1;
        *(float2*)(r + (size_t)c * PDST) = make_float2(rA, rB);
    }
}

// -------------------------------- launch --------------------------------
extern "C" void kernel_launch(void* const* d_in, const int* in_sizes, int n_in,
                              void* d_out, int out_size) {
    const float* c1 = (const float*)d_in[0];
    const float* c2 = (const float*)d_in[1];
    const float* out = (const float*)d_in[2];
    const float* W1 = (const float*)d_in[3];
    const float* b1 = (const float*)d_in[4];
    const float* W2 = (const float*)d_in[5];
    const float* b2 = (const float*)d_in[6];
    float* res = (float*)d_out;

    transpose_out_kernel<<<dim3(4, 4, NB * COUT), dim3(32, 8)>>>(out);
    gemmK_kernel<<<dim3(PSRC / 128, NB), 256>>>(c2, W2, b2);
    gemmM_kernel<<<dim3(PSRC / 128, C1CH / 64, NB), 256>>>(W1, b1);
    energy_kernel<<<dim3(HD, NB), 256>>>(c1);
    apply_kernel<<<dim3(HD, 2, NB), 256>>>(res);
}